// round 2
// baseline (speedup 1.0000x reference)
#include <cuda_runtime.h>

// diff_lpc2rc: x shape (64, 32768, 16) fp32. Per row v[0..15]:
//   for i = 1..15:  m = 16 - i; k = v[m];
//     v[t] = (v[t] - k * v[m-1-t]) / (1 - k*k)   for t in [0, m)
// Rows are independent -> 1 thread per row, fully unrolled in registers.

#define NCOEF 16

__device__ __forceinline__ float fast_rcp(float x) {
    float r;
    asm("rcp.approx.ftz.f32 %0, %1;" : "=f"(r) : "f"(x));
    return r;
}

__global__ __launch_bounds__(256) void diff_lpc2rc_kernel(
    const float* __restrict__ x, float* __restrict__ out, int nrows)
{
    int r = blockIdx.x * blockDim.x + threadIdx.x;
    if (r >= nrows) return;

    const float4* in4 = reinterpret_cast<const float4*>(x) + (size_t)r * 4;
    float4 q0 = in4[0];
    float4 q1 = in4[1];
    float4 q2 = in4[2];
    float4 q3 = in4[3];

    float v[NCOEF];
    v[0]  = q0.x; v[1]  = q0.y; v[2]  = q0.z; v[3]  = q0.w;
    v[4]  = q1.x; v[5]  = q1.y; v[6]  = q1.z; v[7]  = q1.w;
    v[8]  = q2.x; v[9]  = q2.y; v[10] = q2.z; v[11] = q2.w;
    v[12] = q3.x; v[13] = q3.y; v[14] = q3.z; v[15] = q3.w;

    #pragma unroll
    for (int i = 1; i < NCOEF; ++i) {
        const int m = NCOEF - i;          // length of active prefix; k = v[m]
        const float k  = v[m];
        const float nk = -k;
        const float inv = fast_rcp(fmaf(nk, k, 1.0f));   // 1/(1 - k^2)

        // pairwise in-place: (t, m-1-t) read each other, so compute both
        // before writing. middle element (odd m) uses a == b.
        #pragma unroll
        for (int t = 0; t < m / 2; ++t) {
            const float a = v[t];
            const float b = v[m - 1 - t];
            v[t]         = fmaf(nk, b, a) * inv;
            v[m - 1 - t] = fmaf(nk, a, b) * inv;
        }
        if (m & 1) {
            const int t = m / 2;
            const float a = v[t];
            v[t] = fmaf(nk, a, a) * inv;   // a*(1-k)/(1-k^2) = a/(1+k)
        }
    }

    q0 = make_float4(v[0],  v[1],  v[2],  v[3]);
    q1 = make_float4(v[4],  v[5],  v[6],  v[7]);
    q2 = make_float4(v[8],  v[9],  v[10], v[11]);
    q3 = make_float4(v[12], v[13], v[14], v[15]);

    float4* out4 = reinterpret_cast<float4*>(out) + (size_t)r * 4;
    out4[0] = q0;
    out4[1] = q1;
    out4[2] = q2;
    out4[3] = q3;
}

extern "C" void kernel_launch(void* const* d_in, const int* in_sizes, int n_in,
                              void* d_out, int out_size)
{
    const float* x = (const float*)d_in[0];
    float* out = (float*)d_out;
    const int nrows = in_sizes[0] / NCOEF;   // 2,097,152
    const int threads = 256;
    const int blocks = (nrows + threads - 1) / threads;
    diff_lpc2rc_kernel<<<blocks, threads>>>(x, out, nrows);
}